// round 11
// baseline (speedup 1.0000x reference)
#include <cuda_runtime.h>

#define S_GRID 28
#define SS 784            // 28*28
#define NC 80
#define BB 2
#define MAXB 50
#define PRED_C 90         // BB*5 + NC

__device__ float g_partial[4096];
__device__ int   g_count = 0;

__global__ __launch_bounds__(256) void yolo_loss_kernel(
    const float* __restrict__ pred,
    const float* __restrict__ tgt,
    float* __restrict__ out,
    int batch)
{
    const int b   = blockIdx.x;
    const int tid = threadIdx.x;
    const float cell = 1.0f / 28.0f;
    const float* pb = pred + (size_t)b * SS * PRED_C;

    __shared__ float  s_traw[MAXB * 5];     // staged targets (250 floats)
    __shared__ float  s_clsst[MAXB * NC];   // staged class rows (16 KB)
    __shared__ int    s_cell[MAXB];         // -1 = invalid
    __shared__ float  s_best[MAXB];
    __shared__ float4 s_gbox[MAXB];         // gt: cx_rel, cy_rel, w, h
    __shared__ float4 s_pbox[MAXB];         // responsible pred box
    __shared__ float  s_pconf[MAXB];
    __shared__ int    s_cid[MAXB];
    __shared__ unsigned char s_win[MAXB];
    __shared__ int    s_obj[MAXB];
    __shared__ int    s_nobj;
    __shared__ unsigned s_mask[MAXB][3];
    __shared__ float  s_red[8];

    // ---- round 1a: coalesced staged target load (issued first) ----
    if (tid < 125) {
        const float2* tt2 = reinterpret_cast<const float2*>(tgt + (size_t)b * MAXB * 5);
        float2 v = __ldg(tt2 + tid);
        s_traw[2 * tid]     = v.x;
        s_traw[2 * tid + 1] = v.y;
    }

    // ---- round 1b: noobj sweep, all 8 loads in flight before any use ----
    float x0 = __ldg(pb + (tid      ) * PRED_C + 4);
    float y0 = __ldg(pb + (tid      ) * PRED_C + 9);
    float x1 = __ldg(pb + (tid + 256) * PRED_C + 4);
    float y1 = __ldg(pb + (tid + 256) * PRED_C + 9);
    float x2 = __ldg(pb + (tid + 512) * PRED_C + 4);
    float y2 = __ldg(pb + (tid + 512) * PRED_C + 9);
    float x3 = 0.f, y3 = 0.f;
    if (tid < SS - 768) {
        x3 = __ldg(pb + (tid + 768) * PRED_C + 4);
        y3 = __ldg(pb + (tid + 768) * PRED_C + 9);
    }

    __syncthreads();   // s_traw ready

    // ---- cell indices: depend ONLY on targets (cheap, no loads) ----
    if (tid < MAXB) {
        float tcls = s_traw[tid * 5 + 0];
        if (tcls >= 0.0f) {
            float tcx = s_traw[tid * 5 + 1], tcy = s_traw[tid * 5 + 2];
            float tw  = s_traw[tid * 5 + 3], th  = s_traw[tid * 5 + 4];
            int col = min((int)(tcx / cell), S_GRID - 1);
            int row = min((int)(tcy / cell), S_GRID - 1);
            s_cell[tid] = row * S_GRID + col;
            s_cid[tid]  = min(max((int)tcls, 0), NC - 1);
            s_gbox[tid] = make_float4(tcx / cell - (float)col,
                                      tcy / cell - (float)row, tw, th);
        } else {
            s_cell[tid] = -1;
        }
    }
    __syncthreads();   // s_cell ready

    // ---- round 2: warp-specialized concurrent prefetch ----
    if (tid >= 64) {
        // warps 2..7: stage candidate class rows (float2, independent, high MLP)
        for (int k = tid - 64; k < MAXB * (NC / 2); k += 192) {
            int t = k / (NC / 2);
            int j = k - t * (NC / 2);
            int cc = s_cell[t];
            if (cc >= 0) {
                const float2* cls2 =
                    reinterpret_cast<const float2*>(pb + (size_t)cc * PRED_C + BB * 5);
                float2 v = __ldg(cls2 + j);
                *reinterpret_cast<float2*>(&s_clsst[t * NC + 2 * j]) = v;
            }
        }
    } else if (tid < MAXB) {
        // warps 0..1: phase-1 IoU vs both boxes; stash responsible box in SMEM
        int cc = s_cell[tid];
        if (cc >= 0) {
            float tcx = s_traw[tid * 5 + 1], tcy = s_traw[tid * 5 + 2];
            float tw  = s_traw[tid * 5 + 3], th  = s_traw[tid * 5 + 4];
            int col = cc % S_GRID, row = cc / S_GRID;
            const float2* pp2 = reinterpret_cast<const float2*>(pb + (size_t)cc * PRED_C);
            float2 v0 = __ldg(pp2 + 0);   // x0 y0
            float2 v1 = __ldg(pp2 + 1);   // w0 h0
            float2 v2 = __ldg(pp2 + 2);   // c0 x1
            float2 v3 = __ldg(pp2 + 3);   // y1 w1
            float2 v4 = __ldg(pp2 + 4);   // h1 c1
            float bxj[2] = {v0.x, v2.y};
            float byj[2] = {v0.y, v3.x};
            float bwj[2] = {v1.x, v3.y};
            float bhj[2] = {v1.y, v4.x};
            float bcj[2] = {v2.x, v4.y};

            float gx1 = tcx - tw * .5f, gy1 = tcy - th * .5f;
            float gx2 = tcx + tw * .5f, gy2 = tcy + th * .5f;
            float garea = fmaxf(gx2 - gx1, 0.f) * fmaxf(gy2 - gy1, 0.f);
            float iou[2];
            #pragma unroll
            for (int j = 0; j < 2; j++) {
                float px = (bxj[j] + (float)col) * cell;
                float py = (byj[j] + (float)row) * cell;
                float pw = bwj[j], ph = bhj[j];
                float px1 = px - pw * .5f, py1 = py - ph * .5f;
                float px2 = px + pw * .5f, py2 = py + ph * .5f;
                float iw = fmaxf(fminf(px2, gx2) - fmaxf(px1, gx1), 0.f);
                float ih = fmaxf(fminf(py2, gy2) - fmaxf(py1, gy1), 0.f);
                float inter = iw * ih;
                float uni = fmaxf(px2 - px1, 0.f) * fmaxf(py2 - py1, 0.f)
                          + garea - inter;
                iou[j] = inter / (uni + 1e-6f);
            }
            int r = (iou[1] > iou[0]) ? 1 : 0;      // first-index tie break
            s_best[tid]  = fmaxf(iou[0], iou[1]);
            s_pbox[tid]  = make_float4(bxj[r], byj[r], bwj[r], bhj[r]);
            s_pconf[tid] = bcj[r];
        }
    }

    // consume sweep (overlaps the round-2 flight of other warps)
    float acc_noobj = ((x0 * x0 + y0 * y0) + (x1 * x1 + y1 * y1))
                    + ((x2 * x2 + y2 * y2) + (x3 * x3 + y3 * y3));
    __syncthreads();   // phase-1 results + class stage ready

    // ---- winner per cell = first index achieving max best (scan semantics) ----
    if (tid < MAXB) {
        bool win = (s_cell[tid] >= 0);
        if (win) {
            int myc = s_cell[tid]; float myb = s_best[tid];
            for (int s = 0; s < MAXB; s++) {
                if (s == tid || s_cell[s] != myc) continue;
                float ob = s_best[s];
                if (ob > myb || (ob == myb && s < tid)) { win = false; break; }
            }
        }
        s_win[tid] = win ? 1 : 0;
    }
    __syncthreads();

    // ---- deterministic compaction (warp 0, two ballots) ----
    if (tid < 32) {
        unsigned lt = (1u << tid) - 1u;
        bool p0 = s_win[tid] != 0;
        unsigned m0 = __ballot_sync(0xffffffffu, p0);
        if (p0) s_obj[__popc(m0 & lt)] = tid;
        int c0 = __popc(m0);
        bool p1 = (tid < MAXB - 32) && (s_win[32 + tid] != 0);
        unsigned m1 = __ballot_sync(0xffffffffu, p1);
        if (p1) s_obj[c0 + __popc(m1 & lt)] = 32 + tid;
        if (tid == 0) s_nobj = c0 + __popc(m1);
    }
    __syncthreads();
    const int nobj = s_nobj;

    // ---- per-winner class masks (union over all targets sharing the cell) ----
    if (tid < nobj) {
        int t = s_obj[tid];
        int myc = s_cell[t];
        unsigned m0 = 0u, m1 = 0u, m2 = 0u;
        for (int s = 0; s < MAXB; s++) {
            if (s_cell[s] == myc) {
                int ci = s_cid[s];
                if (ci < 32)      m0 |= 1u << ci;
                else if (ci < 64) m1 |= 1u << (ci - 32);
                else              m2 |= 1u << (ci - 64);
            }
        }
        s_mask[tid][0] = m0; s_mask[tid][1] = m1; s_mask[tid][2] = m2;
    }
    __syncthreads();

    float acc_obj = 0.f, acc_coord = 0.f, acc_cls = 0.f;

    // ---- CIoU + obj conf + noobj correction: 100% SMEM ----
    for (int i = tid; i < nobj; i += 256) {
        int t = s_obj[i];
        int c = s_cell[t];
        float4 p = s_pbox[t];
        float bc = s_pconf[t];
        acc_noobj -= bc * bc;                 // responsible box excluded
        float d = bc - s_best[t];
        acc_obj += d * d;

        int row = c / S_GRID, col = c % S_GRID;
        float4 g = s_gbox[t];
        float px = (p.x + (float)col) * cell, py = (p.y + (float)row) * cell;
        float pw = fabsf(p.z), ph = fabsf(p.w);
        float gx = (g.x + (float)col) * cell, gy = (g.y + (float)row) * cell;
        float gw = g.z, gh = g.w;

        float px1 = px - pw * .5f, py1 = py - ph * .5f;
        float px2 = px + pw * .5f, py2 = py + ph * .5f;
        float gx1 = gx - gw * .5f, gy1 = gy - gh * .5f;
        float gx2 = gx + gw * .5f, gy2 = gy + gh * .5f;
        float iw = fmaxf(fminf(px2, gx2) - fmaxf(px1, gx1), 0.f);
        float ih = fmaxf(fminf(py2, gy2) - fmaxf(py1, gy1), 0.f);
        float inter = iw * ih;
        float ap = fmaxf(px2 - px1, 0.f) * fmaxf(py2 - py1, 0.f);
        float ag = fmaxf(gx2 - gx1, 0.f) * fmaxf(gy2 - gy1, 0.f);
        float uni = ap + ag - inter;
        float iou = inter / (uni + 1e-7f);
        float rho2 = (px - gx) * (px - gx) + (py - gy) * (py - gy);
        float cw = fmaxf(px2, gx2) - fminf(px1, gx1);
        float ch = fmaxf(py2, gy2) - fminf(py1, gy1);
        float c2 = cw * cw + ch * ch + 1e-7f;
        float dv = atanf(gw / (gh + 1e-7f)) - atanf(pw / (ph + 1e-7f));
        float v = 0.40528473456935108577f * dv * dv;   // 4/pi^2
        float alpha = v / (1.0f - iou + v + 1e-7f);
        acc_coord += 1.0f - iou + rho2 / c2 + alpha * v;
    }

    // ---- class BCE: 100% SMEM (staged rows), conflict-free stride-1 LDS ----
    for (int idx = tid; idx < nobj * NC; idx += 256) {
        int i  = idx / NC;
        int cc = idx - i * NC;
        int t  = s_obj[i];
        float x = s_clsst[t * NC + cc];
        float gflag = ((s_mask[i][cc >> 5] >> (cc & 31)) & 1u) ? 1.0f : 0.0f;
        acc_cls += fmaxf(x, 0.0f) - x * gflag + log1pf(__expf(-fabsf(x)));
    }

    // ---- block reduction: shuffle within warp, fixed-order across warps ----
    float total = 5.0f * acc_coord + acc_obj + 0.1f * acc_noobj + acc_cls;
    #pragma unroll
    for (int off = 16; off > 0; off >>= 1)
        total += __shfl_down_sync(0xffffffffu, total, off);
    if ((tid & 31) == 0) s_red[tid >> 5] = total;
    __syncthreads();
    if (tid == 0) {
        float v = ((s_red[0] + s_red[1]) + (s_red[2] + s_red[3]))
                + ((s_red[4] + s_red[5]) + (s_red[6] + s_red[7]));
        g_partial[b] = v;
        __threadfence();
    }
    __syncthreads();

    // ---- last block: fixed-order final reduction (deterministic) ----
    __shared__ int s_last;
    if (tid == 0) s_last = (atomicAdd(&g_count, 1) == batch - 1) ? 1 : 0;
    __syncthreads();
    if (s_last) {
        __shared__ float s_fin[256];
        float v = 0.0f;
        for (int i = tid; i < batch; i += 256) v += g_partial[i];
        s_fin[tid] = v;
        __syncthreads();
        #pragma unroll
        for (int k = 128; k > 0; k >>= 1) {
            if (tid < k) s_fin[tid] += s_fin[tid + k];
            __syncthreads();
        }
        if (tid == 0) {
            out[0] = s_fin[0] / (float)batch;
            g_count = 0;                     // reset for next graph replay
        }
    }
}

extern "C" void kernel_launch(void* const* d_in, const int* in_sizes, int n_in,
                              void* d_out, int out_size)
{
    const float* pred = (const float*)d_in[0];
    const float* tgt  = (const float*)d_in[1];
    int batch = in_sizes[0] / (SS * PRED_C);
    if (batch > 4096) batch = 4096;
    yolo_loss_kernel<<<batch, 256>>>(pred, tgt, (float*)d_out, batch);
}

// round 12
// speedup vs baseline: 1.4047x; 1.4047x over previous
#include <cuda_runtime.h>

#define S_GRID 28
#define SS 784            // 28*28
#define NC 80
#define BB 2
#define MAXB 50
#define PRED_C 90         // BB*5 + NC

__device__ float g_partial[4096];
__device__ int   g_count = 0;

__global__ __launch_bounds__(256) void yolo_loss_kernel(
    const float* __restrict__ pred,
    const float* __restrict__ tgt,
    float* __restrict__ out,
    int batch)
{
    const int b   = blockIdx.x;
    const int tid = threadIdx.x;

    __shared__ unsigned long long s_key[SS];   // (bits(best)<<32)|(63-t); 0 = empty
    __shared__ float4   s_gtbox[SS];
    __shared__ float    s_bestiou[SS];
    __shared__ int      s_resp[SS];            // winner's best box idx
    __shared__ unsigned s_cls[SS][3];          // 80-bit class mask
    __shared__ int      s_objlist[MAXB + 2];
    __shared__ int      s_nobj;
    __shared__ float    s_red[8];

    const float cell = 1.0f / 28.0f;
    const float* pb = pred + (size_t)b * SS * PRED_C;

    // ---- issue the target loads ASAP (2-deep dependent DRAM chain) ----
    float t0 = 0.f, t1 = 0.f, t2 = 0.f, t3 = 0.f, t4 = -1.f;
    if (tid < MAXB) {
        const float* tt = tgt + ((size_t)b * MAXB + tid) * 5;
        t4 = tt[0]; t0 = tt[1]; t1 = tt[2]; t2 = tt[3]; t3 = tt[4];
    }

    // ---- noobj conf sweep: lane-PAIR mapping for minimal L1tex wavefronts ----
    // task j -> cell j>>1, conf offset 4 (even j) or 9 (odd j). Lane pairs hit
    // the SAME row (both confs usually in one 128B line): ~16-20 lines per
    // warp-LDG instead of 32. 7 independent loads per thread (MLP=7).
    float acc_noobj = 0.0f;
    #pragma unroll
    for (int k = 0; k < 7; k++) {
        int j = tid + k * 256;
        if (j < 2 * SS) {
            int c   = j >> 1;
            int off = (j & 1) ? 9 : 4;
            float v = __ldg(pb + c * PRED_C + off);
            acc_noobj += v * v;
        }
    }

    // ---- SMEM init ----
    for (int c = tid; c < SS; c += 256) {
        s_key[c]  = 0ull;
        s_resp[c] = -1;
        s_cls[c][0] = 0u; s_cls[c][1] = 0u; s_cls[c][2] = 0u;
    }
    __syncthreads();

    // ---- per-target precompute + atomicMax race (replaces serial scan) ----
    int   my_cell = -1, my_bestj = 0;
    float my_best = 0.f;
    float4 my_box;
    unsigned long long my_key = 0ull;
    if (tid < MAXB && t4 >= 0.0f) {
        float cx = t0, cy = t1, w = t2, h = t3;
        int ci  = min(max((int)t4, 0), NC - 1);
        int col = min((int)(cx / cell), S_GRID - 1);
        int row = min((int)(cy / cell), S_GRID - 1);
        float cxr = cx / cell - (float)col;
        float cyr = cy / cell - (float)row;
        my_cell = row * S_GRID + col;
        my_box  = make_float4(cxr, cyr, w, h);

        const float* pp = pb + my_cell * PRED_C;
        float gx1 = cx - w * 0.5f, gy1 = cy - h * 0.5f;
        float gx2 = cx + w * 0.5f, gy2 = cy + h * 0.5f;
        float garea = fmaxf(gx2 - gx1, 0.0f) * fmaxf(gy2 - gy1, 0.0f);
        float iou[2];
        #pragma unroll
        for (int j = 0; j < 2; j++) {
            float px = (pp[5*j + 0] + (float)col) * cell;
            float py = (pp[5*j + 1] + (float)row) * cell;
            float pw = pp[5*j + 2], ph = pp[5*j + 3];
            float px1 = px - pw * 0.5f, py1 = py - ph * 0.5f;
            float px2 = px + pw * 0.5f, py2 = py + ph * 0.5f;
            float iw = fmaxf(fminf(px2, gx2) - fmaxf(px1, gx1), 0.0f);
            float ih = fmaxf(fminf(py2, gy2) - fmaxf(py1, gy1), 0.0f);
            float inter = iw * ih;
            float uni = fmaxf(px2 - px1, 0.0f) * fmaxf(py2 - py1, 0.0f)
                      + garea - inter;
            iou[j] = inter / (uni + 1e-6f);
        }
        my_bestj = (iou[1] > iou[0]) ? 1 : 0;      // first-index tie break
        my_best  = fmaxf(iou[0], iou[1]);
        // scan semantics == first index achieving the max best per cell:
        // strictly-greater steals; equal does not. Key orders by (best, -t).
        my_key = ((unsigned long long)__float_as_uint(my_best) << 32)
               | (unsigned long long)(63 - tid);
        atomicMax(&s_key[my_cell], my_key);
        atomicOr(&s_cls[my_cell][ci >> 5], 1u << (ci & 31));
    }
    __syncthreads();

    // winners write their cell state (unique per cell)
    if (my_key != 0ull && s_key[my_cell] == my_key) {
        s_gtbox[my_cell]   = my_box;
        s_bestiou[my_cell] = my_best;
        s_resp[my_cell]    = my_bestj;
    }
    __syncthreads();

    // ---- deterministic compaction of object cells (warp 0 ballot scan) ----
    if (tid < 32) {
        int count = 0;
        #pragma unroll
        for (int cb = 0; cb < SS; cb += 32) {
            int c = cb + tid;
            bool p = (c < SS) && (s_resp[c] >= 0);
            unsigned m = __ballot_sync(0xffffffffu, p);
            if (p) s_objlist[count + __popc(m & ((1u << tid) - 1u))] = c;
            count += __popc(m);
        }
        if (tid == 0) s_nobj = count;
    }
    __syncthreads();
    const int nobj = s_nobj;

    float acc_obj = 0.0f, acc_coord = 0.0f, acc_cls = 0.0f;

    // ---- object cells: CIoU + obj conf + noobj correction ----
    for (int i = tid; i < nobj; i += 256) {
        int c = s_objlist[i];
        const float* pp = pb + c * PRED_C;
        int r = s_resp[c];
        float bx = pp[5*r + 0], by = pp[5*r + 1];
        float bw = pp[5*r + 2], bh = pp[5*r + 3], bc = pp[5*r + 4];
        acc_noobj -= bc * bc;                 // responsible box excluded
        float d = bc - s_bestiou[c];
        acc_obj += d * d;

        int row = c / S_GRID, col = c % S_GRID;
        float4 g = s_gtbox[c];
        float px = (bx + (float)col) * cell, py = (by + (float)row) * cell;
        float pw = fabsf(bw), ph = fabsf(bh);
        float gx = (g.x + (float)col) * cell, gy = (g.y + (float)row) * cell;
        float gw = g.z, gh = g.w;

        float px1 = px - pw * 0.5f, py1 = py - ph * 0.5f;
        float px2 = px + pw * 0.5f, py2 = py + ph * 0.5f;
        float gx1 = gx - gw * 0.5f, gy1 = gy - gh * 0.5f;
        float gx2 = gx + gw * 0.5f, gy2 = gy + gh * 0.5f;
        float iw = fmaxf(fminf(px2, gx2) - fmaxf(px1, gx1), 0.0f);
        float ih = fmaxf(fminf(py2, gy2) - fmaxf(py1, gy1), 0.0f);
        float inter = iw * ih;
        float ap = fmaxf(px2 - px1, 0.0f) * fmaxf(py2 - py1, 0.0f);
        float ag = fmaxf(gx2 - gx1, 0.0f) * fmaxf(gy2 - gy1, 0.0f);
        float uni = ap + ag - inter;
        float iou = inter / (uni + 1e-7f);
        float rho2 = (px - gx) * (px - gx) + (py - gy) * (py - gy);
        float cw = fmaxf(px2, gx2) - fminf(px1, gx1);
        float ch = fmaxf(py2, gy2) - fminf(py1, gy1);
        float c2 = cw * cw + ch * ch + 1e-7f;
        float dv = atanf(gw / (gh + 1e-7f)) - atanf(pw / (ph + 1e-7f));
        float v = 0.40528473456935108577f * dv * dv;   // 4/pi^2
        float alpha = v / (1.0f - iou + v + 1e-7f);
        acc_coord += 1.0f - iou + rho2 / c2 + alpha * v;
    }

    // ---- class BCE: float2-vectorized over (obj cell, class pair) ----
    // class region at byte offset 360c + 40 -> 8-byte aligned.
    for (int idx = tid; idx < nobj * (NC / 2); idx += 256) {
        int i = idx / (NC / 2);
        int j = idx - i * (NC / 2);          // classes 2j, 2j+1
        int c = s_objlist[i];
        const float2* cls2 =
            reinterpret_cast<const float2*>(pb + c * PRED_C + BB * 5);
        float2 x2 = __ldg(cls2 + j);
        int c0 = 2 * j, c1 = 2 * j + 1;
        float g0 = ((s_cls[c][c0 >> 5] >> (c0 & 31)) & 1u) ? 1.0f : 0.0f;
        float g1 = ((s_cls[c][c1 >> 5] >> (c1 & 31)) & 1u) ? 1.0f : 0.0f;
        acc_cls += fmaxf(x2.x, 0.0f) - x2.x * g0 + log1pf(__expf(-fabsf(x2.x)));
        acc_cls += fmaxf(x2.y, 0.0f) - x2.y * g1 + log1pf(__expf(-fabsf(x2.y)));
    }

    // ---- block reduction: shuffle within warp, tree across warps ----
    float total = 5.0f * acc_coord + acc_obj + 0.1f * acc_noobj + acc_cls;
    #pragma unroll
    for (int off = 16; off > 0; off >>= 1)
        total += __shfl_down_sync(0xffffffffu, total, off);
    if ((tid & 31) == 0) s_red[tid >> 5] = total;
    __syncthreads();
    if (tid == 0) {
        float v = ((s_red[0] + s_red[1]) + (s_red[2] + s_red[3]))
                + ((s_red[4] + s_red[5]) + (s_red[6] + s_red[7]));
        g_partial[b] = v;
        __threadfence();
    }
    __syncthreads();

    // ---- last block performs the final deterministic reduction ----
    __shared__ int s_last;
    if (tid == 0) s_last = (atomicAdd(&g_count, 1) == batch - 1) ? 1 : 0;
    __syncthreads();
    if (s_last) {
        // fixed-order tree over g_partial: value is replay-deterministic
        __shared__ float s_fin[256];
        float v = 0.0f;
        for (int i = tid; i < batch; i += 256) v += g_partial[i];
        s_fin[tid] = v;
        __syncthreads();
        #pragma unroll
        for (int k = 128; k > 0; k >>= 1) {
            if (tid < k) s_fin[tid] += s_fin[tid + k];
            __syncthreads();
        }
        if (tid == 0) {
            out[0] = s_fin[0] / (float)batch;
            g_count = 0;                        // reset for next graph replay
        }
    }
}

extern "C" void kernel_launch(void* const* d_in, const int* in_sizes, int n_in,
                              void* d_out, int out_size)
{
    const float* pred = (const float*)d_in[0];
    const float* tgt  = (const float*)d_in[1];
    int batch = in_sizes[0] / (SS * PRED_C);
    if (batch > 4096) batch = 4096;
    yolo_loss_kernel<<<batch, 256>>>(pred, tgt, (float*)d_out, batch);
}